// round 7
// baseline (speedup 1.0000x reference)
#include <cuda_runtime.h>
#include <math.h>

// Problem constants (fixed by setup_inputs)
#define Bb 16
#define Mm 64
#define Nn 21504          // 128^2 + 64^2 + 32^2
#define Cc 15
#define Aa 91             // ANGLE_BINS + 1
#define KTOP 13
#define NTOT (Bb*Nn)      // 344064
#define NREC (Bb*Mm*KTOP) // 13312
#define NC 736            // max in-box candidates (area/64+perim/8 bound = 598)
#define NF4 (NTOT*Cc/4)   // 1290240 float4 of cls; = 120 * 10752 blocks
#define ANGLE_SCALE_F 0.017453292519943295f  // pi/2/90
#define FULLM 0xffffffffu

// ------------------------------------------------------------------ scratch
__device__ float    d_pred[(size_t)NTOT*8];   // {x,y,va,vb},{vc,det,Z,0}
__device__ int2     d_claim[NTOT];            // .x = cnt, .y = max(INT_MAX-m); 0 = unclaimed
__device__ float4   d_gprep[Bb*Mm*4];         // q0{gx,gy,va,vb} q1{vc,det,r,lw} q2{ca,sa,hw,hh} q3{li,lbl,vmask,-}
__device__ uint2    d_maxAI[Bb*Mm];           // .x = max align bits, .y = max iou bits
__device__ float    d_acc[8];                 // 0 cls, 1 score_sum, 2 box, 3 angle, 4 npos
__device__ int      d_listcnt;
__device__ float4   d_rec[NREC];              // {gi, m, align, hd}
__device__ int      d_ecount;
__device__ float4   d_e[NREC];                // {gi, bm, align, hd}
__device__ unsigned d_done;

// ------------------------------------------------------------------ helpers
__device__ __forceinline__ float probiou_pre(
    float x1, float y1, float a1, float b1, float c1, float det1,
    float x2, float y2, float a2, float b2, float c2, float det2) {
    const float eps = 1e-3f;
    float as = a1 + a2, bs = b1 + b2, cs = c1 + c2;
    float dx = x1 - x2, dy = y1 - y2;
    float denom = as * bs - cs * cs + eps;
    float rden = __fdividef(1.f, denom);
    float t1 = (as * dy * dy + bs * dx * dx) * rden * 0.25f;
    float t2 = cs * (x2 - x1) * (y1 - y2) * rden * 0.5f;
    float t3 = 0.5f * __logf(denom * __fdividef(1.f, 4.f * sqrtf(det1 * det2) + eps) + eps);
    float bd = fminf(fmaxf(t1 + t2 + t3, eps), 100.f);
    return sqrtf(1.f - __expf(-bd) + 1e-7f);
}

__device__ __forceinline__ float warpSum(float v) {
    #pragma unroll
    for (int o = 16; o; o >>= 1) v += __shfl_xor_sync(FULLM, v, o);
    return v;
}

__device__ __forceinline__ float focal_bg(float x) {
    float e = __expf(-fabsf(x));
    float den = 1.f + e;
    float rden = __fdividef(1.f, den);
    float p = (x >= 0.f) ? rden : e * rden;
    float bce = fmaxf(x, 0.f) + __logf(den);
    return bce * 0.75f * p * p;
}

// ------------------------------------------------------------------ kernels
// Per-gt precompute + maxAI reset (claim array reset incrementally by the
// previous replay's finalizer; zero-state is valid).
__global__ void __launch_bounds__(256) k_init(const float* __restrict__ gbox,
                                              const int*   __restrict__ glab,
                                              const float* __restrict__ vmask) {
    int i = blockIdx.x * 256 + threadIdx.x;
    if (i < Bb * Mm) {
        float gx = gbox[i * 5 + 0], gy = gbox[i * 5 + 1];
        float gw = gbox[i * 5 + 2], gh = gbox[i * 5 + 3], ga = gbox[i * 5 + 4];
        float ca, sa; __sincosf(ga, &sa, &ca);
        float A = gw * gw * (1.f/12.f), B = gh * gh * (1.f/12.f);
        float va = A * ca * ca + B * sa * sa;
        float vb = A * sa * sa + B * ca * ca;
        float vc = (A - B) * ca * sa;
        float det = fmaxf(va * vb - vc * vc, 0.f);
        float r = 0.5f * sqrtf(gw * gw + gh * gh);
        float t = fminf(fmaxf(ga / ANGLE_SCALE_F, 0.f), 89.99f);
        int li = (int)t;
        int ri = min(li + 1, 90);
        float lw = (float)ri - t;
        d_gprep[i * 4 + 0] = make_float4(gx, gy, va, vb);
        d_gprep[i * 4 + 1] = make_float4(vc, det, r, lw);
        d_gprep[i * 4 + 2] = make_float4(ca, sa, gw * 0.5f, gh * 0.5f);
        d_gprep[i * 4 + 3] = make_float4(__int_as_float(li), __int_as_float(glab[i]),
                                         vmask[i], 0.f);
        d_maxAI[i] = make_uint2(0u, 0u);
    }
}

// Warp per 4 anchors, 8 lanes per anchor. Also fuses the background
// focal-BCE for this block's 120 float4 of cls (contiguous 1920B slice).
__global__ void __launch_bounds__(256) k_decode(const float* __restrict__ reg,
                                                const float* __restrict__ ang,
                                                const float4* __restrict__ cls4) {
    __shared__ float sw[8];
    int tid = threadIdx.x;
    int wid = tid >> 5, lane = tid & 31;
    int abase = blockIdx.x * 32 + wid * 4;
    int j = lane >> 3;          // anchor within group
    int s = lane & 7;           // sub-lane within anchor
    int ga = abase + j;
    const float* row = ang + (size_t)ga * Aa;

    float ssum = 0.f, wsum = 0.f;
    float fi = (float)s;
    #pragma unroll
    for (int k = 0; k < 11; k++) {
        float p = __expf(row[s + 8 * k]);
        ssum += p;
        wsum = fmaf(fi, p, wsum);
        fi += 8.f;
    }
    if (s < 3) {
        float p = __expf(row[s + 88]);
        ssum += p;
        wsum = fmaf((float)(s + 88), p, wsum);
    }
    #pragma unroll
    for (int o = 4; o; o >>= 1) {
        ssum += __shfl_xor_sync(FULLM, ssum, o);
        wsum += __shfl_xor_sync(FULLM, wsum, o);
    }

    if (s == 0) {
        float angle = ANGLE_SCALE_F * __fdividef(wsum, ssum);
        float Z = __logf(ssum);
        const float4 rd = ((const float4*)reg)[ga];   // lt=(x,y) rb=(z,w)
        float offx = (rd.z - rd.x) * 0.5f, offy = (rd.w - rd.y) * 0.5f;
        float c, sn; __sincosf(angle, &sn, &c);
        float ox = offx * c - offy * sn;
        float oy = offx * sn + offy * c;
        int n = ga % Nn;
        float ax, ay, st;
        if (n < 16384)      { ax = ((n & 127) + 0.5f) * 8.f;  ay = ((n >> 7) + 0.5f) * 8.f;  st = 8.f;  }
        else if (n < 20480) { int k = n - 16384; ax = ((k & 63) + 0.5f) * 16.f; ay = ((k >> 6) + 0.5f) * 16.f; st = 16.f; }
        else                { int k = n - 20480; ax = ((k & 31) + 0.5f) * 32.f; ay = ((k >> 5) + 0.5f) * 32.f; st = 32.f; }
        float X = ox * st + ax, Y = oy * st + ay;
        float W = (rd.x + rd.z) * st, H = (rd.y + rd.w) * st;
        float A = W * W * (1.f/12.f), B = H * H * (1.f/12.f);
        float va = A * c * c + B * sn * sn;
        float vb = A * sn * sn + B * c * c;
        float vc = (A - B) * c * sn;
        float det = fmaxf(va * vb - vc * vc, 0.f);
        float4* pp = (float4*)(d_pred + (size_t)ga * 8);
        pp[0] = make_float4(X, Y, va, vb);
        pp[1] = make_float4(vc, det, Z, 0.f);
    }

    // fused background focal-BCE: this block's 120 float4 of cls
    float acc = 0.f;
    if (tid < 120) {
        float4 v = cls4[(size_t)blockIdx.x * 120 + tid];
        acc = focal_bg(v.x) + focal_bg(v.y) + focal_bg(v.z) + focal_bg(v.w);
    }
    acc = warpSum(acc);
    if (lane == 0) sw[wid] = acc;
    __syncthreads();
    if (tid == 0) {
        float t = 0.f;
        #pragma unroll
        for (int w = 0; w < 8; w++) t += sw[w];
        atomicAdd(&d_acc[0], t);
    }
}

// One block (128 thr) per (b,m). Collect in-box candidate keys (64-bit:
// align desc, index asc) into smem; per-warp exact top-13 (sync-free warp
// argmax rounds over strided quarter); warp 0 merges the <=52 warp winners.
// Only 2 block barriers total.
__global__ void __launch_bounds__(128) k_topk(const float* __restrict__ cls) {
    __shared__ unsigned long long sKey[NC];
    __shared__ unsigned long long sW[52];     // 4 warps x 13 winners
    __shared__ int sCnt;

    int bm = blockIdx.x;
    int b = bm >> 6, m = bm & 63;
    const float4 q0 = d_gprep[bm * 4 + 0];
    const float4 q1 = d_gprep[bm * 4 + 1];
    const float4 q2 = d_gprep[bm * 4 + 2];
    const float4 q3 = d_gprep[bm * 4 + 3];
    if (q3.z == 0.f) return;      // pad gt

    const float gx = q0.x, gy = q0.y, gva = q0.z, gvb = q0.w;
    const float gvc = q1.x, gdet = q1.y, r = q1.z;
    const float ca = q2.x, sa = q2.y, hw = q2.z, hh = q2.w;
    const int lbl = __float_as_int(q3.y);

    int tid = threadIdx.x;
    int wid = tid >> 5, lane = tid & 31;
    if (tid == 0) sCnt = 0;
    if (tid < 52) sW[tid] = 0ull;
    __syncthreads();

    const int   baseL[3] = {0, 16384, 20480};
    const int   ngL[3]   = {128, 64, 32};
    const float sL[3]    = {8.f, 16.f, 32.f};
    #pragma unroll
    for (int L = 0; L < 3; L++) {
        float s = sL[L]; int ng = ngL[L];
        float inv = 1.f / s;
        int ix0 = max(0,      (int)floorf((gx - r) * inv - 0.5f));
        int ix1 = min(ng - 1, (int)ceilf ((gx + r) * inv - 0.5f));
        int iy0 = max(0,      (int)floorf((gy - r) * inv - 0.5f));
        int iy1 = min(ng - 1, (int)ceilf ((gy + r) * inv - 0.5f));
        if (ix1 < ix0 || iy1 < iy0) continue;
        int W = ix1 - ix0 + 1;
        int tot = W * (iy1 - iy0 + 1);
        for (int t0 = 0; t0 < tot; t0 += 128) {
            int t = t0 + tid;
            bool act = false;
            unsigned long long key = 0ull;
            if (t < tot) {
                int q = t / W;
                int ix = ix0 + (t - q * W);
                int iy = iy0 + q;
                float ax = (ix + 0.5f) * s, ay = (iy + 0.5f) * s;
                float dx = ax - gx, dy = ay - gy;
                float xr = dx * ca + dy * sa;
                float yr = -dx * sa + dy * ca;
                if (fabsf(xr) < hw && fabsf(yr) < hh) {
                    int n = baseL[L] + iy * ng + ix;
                    int gi = b * Nn + n;
                    const float4* pp = (const float4*)(d_pred + (size_t)gi * 8);
                    float4 p0 = pp[0], p1 = pp[1];
                    float hd = probiou_pre(gx, gy, gva, gvb, gvc, gdet,
                                           p0.x, p0.y, p0.z, p0.w, p1.x, p1.y);
                    float iou = fmaxf(1.f - hd, 0.f);
                    float x = cls[(size_t)gi * Cc + lbl];
                    float sg = __fdividef(1.f, 1.f + __expf(-x));
                    float i2 = iou * iou;
                    float al = sg * i2 * i2 * i2;
                    if (al > 1e-9f) {
                        act = true;
                        key = ((unsigned long long)__float_as_uint(al) << 32)
                            | (unsigned)(0x7fffffff - n);
                    }
                }
            }
            unsigned mask = __ballot_sync(FULLM, act);
            if (mask) {
                int base = 0;
                if (lane == 0) base = atomicAdd(&sCnt, __popc(mask));
                base = __shfl_sync(FULLM, base, 0);
                if (act) {
                    int off = base + __popc(mask & ((1u << lane) - 1u));
                    if (off < NC) sKey[off] = key;
                }
            }
        }
    }
    __syncthreads();
    int cnt = min(sCnt, NC);

    // per-warp exact top-13 over its strided quarter (sync-free)
    #pragma unroll 1
    for (int k = 0; k < KTOP; k++) {
        unsigned long long best = 0ull; int bs = -1;
        for (int s = wid * 32 + lane; s < cnt; s += 128) {
            unsigned long long v = sKey[s];
            if (v > best) { best = v; bs = s; }
        }
        #pragma unroll
        for (int o = 16; o; o >>= 1) {
            unsigned long long ov = __shfl_xor_sync(FULLM, best, o);
            int os = __shfl_xor_sync(FULLM, bs, o);
            if (ov > best) { best = ov; bs = os; }
        }
        if (best == 0ull) break;
        if (lane == 0) { sW[wid * KTOP + k] = best; sKey[bs] = 0ull; }
    }
    __syncthreads();

    // warp 0 merges the 52 warp-winners; round-k winner lives in lane k's reg
    if (wid == 0) {
        unsigned long long v0 = (lane < 52) ? sW[lane] : 0ull;
        unsigned long long v1 = (lane + 32 < 52) ? sW[lane + 32] : 0ull;
        unsigned long long mykey = 0ull;
        int nfin = 0;
        #pragma unroll 1
        for (int k = 0; k < KTOP; k++) {
            unsigned long long best = (v0 > v1) ? v0 : v1;
            #pragma unroll
            for (int o = 16; o; o >>= 1) {
                unsigned long long ov = __shfl_xor_sync(FULLM, best, o);
                if (ov > best) best = ov;
            }
            if (best == 0ull) break;
            if (v0 == best) v0 = 0ull;
            if (v1 == best) v1 = 0ull;
            if (lane == k) mykey = best;
            nfin++;
        }
        if (nfin) {
            int base = 0;
            if (lane == 0) base = atomicAdd(&d_listcnt, nfin);
            base = __shfl_sync(FULLM, base, 0);
            if (lane < nfin) {
                int n = 0x7fffffff - (int)(mykey & 0xffffffffu);
                float al = __uint_as_float((unsigned)(mykey >> 32));
                int gi = b * Nn + n;
                atomicAdd(&d_claim[gi].x, 1);
                atomicMax(&d_claim[gi].y, 0x7fffffff - m);
                const float4* pp = (const float4*)(d_pred + (size_t)gi * 8);
                float4 p0 = pp[0], p1 = pp[1];
                float hd = probiou_pre(gx, gy, gva, gvb, gvc, gdet,
                                       p0.x, p0.y, p0.z, p0.w, p1.x, p1.y);
                d_rec[base + lane] = make_float4(__int_as_float(gi), __int_as_float(m),
                                                 al, hd);
            }
        }
    }
}

// Resolve records, accumulate angle-CE/npos, append elected entries.
// Last block: maxima-dependent terms, finalize output, reset claims/counters.
__global__ void __launch_bounds__(256) k_resolve_final(const float* __restrict__ cls,
                                                       const float* __restrict__ ang,
                                                       float* __restrict__ out, int osz) {
    __shared__ bool isLast;
    __shared__ int sEc, sLc;
    __shared__ float sr0[8], sr1[8], sr2[8];
    int tid = threadIdx.x;
    int idx = blockIdx.x * 256 + tid;
    int lane = tid & 31;
    int lc = d_listcnt;
    bool has = idx < lc;
    float4 rec = has ? d_rec[idx] : make_float4(0.f, 0.f, 0.f, 0.f);
    int gi = __float_as_int(rec.x);
    int m  = __float_as_int(rec.y);
    float align = rec.z, hd = rec.w;
    int2 cl = has ? d_claim[gi] : make_int2(0, 0);
    bool elected = has && (cl.y == 0x7fffffff - m);
    bool multi = elected && (cl.x > 1);
    int b = gi / Nn;
    int tgt = m;

    unsigned mb = __ballot_sync(FULLM, multi);
    while (mb) {
        int src = __ffs(mb) - 1; mb &= mb - 1;
        int sgi = __shfl_sync(FULLM, gi, src);
        int sb = sgi / Nn;
        const float4* pp = (const float4*)(d_pred + (size_t)sgi * 8);
        float4 p0 = pp[0], p1 = pp[1];
        float bi = -1.f, bh = 0.f; int bmm = 0;
        #pragma unroll
        for (int j = 0; j < 2; j++) {
            int mm = lane + j * 32;
            float4 g0 = d_gprep[(sb * Mm + mm) * 4 + 0];
            float4 g1 = d_gprep[(sb * Mm + mm) * 4 + 1];
            float h = probiou_pre(g0.x, g0.y, g0.z, g0.w, g1.x, g1.y,
                                  p0.x, p0.y, p0.z, p0.w, p1.x, p1.y);
            float io = fmaxf(1.f - h, 0.f);
            if (io > bi) { bi = io; bh = h; bmm = mm; }
        }
        #pragma unroll
        for (int o = 16; o; o >>= 1) {
            float ov = __shfl_xor_sync(FULLM, bi, o);
            float oh = __shfl_xor_sync(FULLM, bh, o);
            int   om = __shfl_xor_sync(FULLM, bmm, o);
            if (ov > bi || (ov == bi && om < bmm)) { bi = ov; bh = oh; bmm = om; }
        }
        if (lane == src) {
            tgt = bmm; hd = bh;
            int lbl = __float_as_int(d_gprep[(sb * Mm + tgt) * 4 + 3].y);
            float x = cls[(size_t)sgi * Cc + lbl];
            float sg = __fdividef(1.f, 1.f + __expf(-x));
            float i2 = bi * bi;
            align = sg * i2 * i2 * i2;
        }
    }

    float c3 = 0.f, c4 = 0.f;
    int ebm = 0;
    if (elected) {
        ebm = b * Mm + tgt;
        atomicMax(&d_maxAI[ebm].x, __float_as_uint(align));
        atomicMax(&d_maxAI[ebm].y, __float_as_uint(fmaxf(1.f - hd, 0.f)));
        float4 g1 = d_gprep[ebm * 4 + 1];
        float4 g3 = d_gprep[ebm * 4 + 3];
        float lw = g1.w;
        int li = __float_as_int(g3.x);
        int ri = min(li + 1, 90);
        float Z = d_pred[(size_t)gi * 8 + 6];
        const float* xr = ang + (size_t)gi * Aa;
        c3 = (Z - __ldg(xr + li)) * lw + (Z - __ldg(xr + ri)) * (1.f - lw);
        c4 = 1.f;
    }

    // warp-aggregated append of elected entries {gi, bm, align, hd}
    unsigned eb = __ballot_sync(FULLM, elected);
    if (eb) {
        int leader = __ffs(eb) - 1;
        int base = 0;
        if (lane == leader) base = atomicAdd(&d_ecount, __popc(eb));
        base = __shfl_sync(FULLM, base, leader);
        if (elected) {
            int off = __popc(eb & ((1u << lane) - 1u));
            d_e[base + off] = make_float4(__int_as_float(gi), __int_as_float(ebm),
                                          align, hd);
        }
    }
    c3 = warpSum(c3); c4 = warpSum(c4);
    if (lane == 0) { atomicAdd(&d_acc[3], c3); atomicAdd(&d_acc[4], c4); }

    // ---- last-block phase: maxima-dependent terms + finalize + reset ----
    __syncthreads();
    if (tid == 0) {
        __threadfence();
        unsigned prev = atomicAdd(&d_done, 1u);
        isLast = (prev == gridDim.x - 1);
        if (isLast) { __threadfence(); sEc = d_ecount; sLc = d_listcnt; }
    }
    __syncthreads();
    if (!isLast) return;

    int ec = sEc;
    float c0 = 0.f, c1 = 0.f, c2 = 0.f;
    for (int e = tid; e < ec; e += 256) {
        float4 en = d_e[e];
        int egi = __float_as_int(en.x);
        int bm2 = __float_as_int(en.y);
        float al = en.z, h = en.w;
        uint2 mx = d_maxAI[bm2];
        float na = al * __uint_as_float(mx.y) *
                   __fdividef(1.f, __uint_as_float(mx.x) + 1e-9f);
        int lbl = __float_as_int(d_gprep[bm2 * 4 + 3].y);
        float x = cls[(size_t)egi * Cc + lbl];
        float ex = __expf(-fabsf(x));
        float den = 1.f + ex;
        float rden = __fdividef(1.f, den);
        float p = (x >= 0.f) ? rden : ex * rden;
        float bce0 = fmaxf(x, 0.f) + __logf(den);
        c0 += (bce0 - x * na) * na - bce0 * 0.75f * p * p;
        c1 += na;
        c2 += h * na;
    }
    // reset claim entries for next replay (duplicates idempotent)
    for (int e = tid; e < sLc; e += 256) {
        int rgi = __float_as_int(d_rec[e].x);
        d_claim[rgi] = make_int2(0, 0);
    }
    c0 = warpSum(c0); c1 = warpSum(c1); c2 = warpSum(c2);
    int wid = tid >> 5;
    if (lane == 0) { sr0[wid] = c0; sr1[wid] = c1; sr2[wid] = c2; }
    __syncthreads();
    if (tid == 0) {
        float t0 = 0.f, t1 = 0.f, t2 = 0.f;
        #pragma unroll
        for (int w = 0; w < 8; w++) { t0 += sr0[w]; t1 += sr1[w]; t2 += sr2[w]; }
        float clsn = d_acc[0] + t0;
        float ss   = fmaxf(d_acc[1] + t1, 1.f);
        float boxn = d_acc[2] + t2;
        float angn = d_acc[3];
        float npos = fmaxf(d_acc[4], 1.f);
        float lcv = clsn / ss;
        float lbv = boxn / ss;
        float lav = angn / npos;
        float tot = lcv + 2.5f * lbv + 0.05f * lav;
        if (osz >= 4) { out[0] = tot; out[1] = lcv; out[2] = lbv; out[3] = lav; }
        else if (osz >= 1) out[0] = tot;
        // reset for next replay
        #pragma unroll
        for (int i2 = 0; i2 < 8; i2++) d_acc[i2] = 0.f;
        d_listcnt = 0; d_ecount = 0;
        __threadfence();
        d_done = 0u;
    }
}

// ------------------------------------------------------------------ launch
extern "C" void kernel_launch(void* const* d_in, const int* in_sizes, int n_in,
                              void* d_out, int out_size) {
    const float* cls   = (const float*)d_in[0];   // (B,N,C)
    const float* reg   = (const float*)d_in[1];   // (B,N,4)
    const float* ang   = (const float*)d_in[2];   // (B,N,91)
    const int*   glab  = (const int*)  d_in[3];   // (B,M,1)
    const float* gbox  = (const float*)d_in[4];   // (B,M,5)
    const float* vmask = (const float*)d_in[5];   // (B,M,1)
    float* out = (float*)d_out;

    k_init          <<<4, 256>>>(gbox, glab, vmask);                        // idx 0
    k_decode        <<<NTOT / 32, 256>>>(reg, ang, (const float4*)cls);     // idx 1
    k_topk          <<<Bb * Mm, 128>>>(cls);                                // idx 2
    k_resolve_final <<<NREC / 256, 256>>>(cls, ang, out, out_size);         // idx 3 (ncu capture)
}

// round 8
// speedup vs baseline: 1.4216x; 1.4216x over previous
#include <cuda_runtime.h>
#include <math.h>

// Problem constants (fixed by setup_inputs)
#define Bb 16
#define Mm 64
#define Nn 21504          // 128^2 + 64^2 + 32^2
#define Cc 15
#define Aa 91             // ANGLE_BINS + 1
#define KTOP 13
#define NTOT (Bb*Nn)      // 344064
#define NREC (Bb*Mm*KTOP) // 13312
#define NC 736            // max in-box candidates
#define ANGLE_SCALE_F 0.017453292519943295f  // pi/2/90
#define FULLM 0xffffffffu

// ------------------------------------------------------------------ scratch
__device__ float    d_pred[(size_t)NTOT*8];   // {x,y,va,vb},{vc,det,Z,0}
__device__ int2     d_claim[NTOT];            // .x = cnt, .y = max(INT_MAX-m); 0 = unclaimed
__device__ float4   d_gprep[Bb*Mm*4];         // q0{gx,gy,va,vb} q1{vc,det,r,lw} q2{ca,sa,hw,hh} q3{li,lbl,vmask,-}
__device__ uint2    d_maxAI[Bb*Mm];           // .x = max align bits, .y = max iou bits
__device__ float    d_acc[8];                 // 0 cls, 1 score_sum, 2 box, 3 angle, 4 npos
__device__ int      d_listcnt;
__device__ float4   d_rec[NREC];              // {gi, m, align, hd}
__device__ int      d_ecount;
__device__ float4   d_e[NREC];                // {gi, bm, align, hd}
__device__ unsigned d_done;

// ------------------------------------------------------------------ helpers
__device__ __forceinline__ float probiou_pre(
    float x1, float y1, float a1, float b1, float c1, float det1,
    float x2, float y2, float a2, float b2, float c2, float det2) {
    const float eps = 1e-3f;
    float as = a1 + a2, bs = b1 + b2, cs = c1 + c2;
    float dx = x1 - x2, dy = y1 - y2;
    float denom = as * bs - cs * cs + eps;
    float rden = __fdividef(1.f, denom);
    float t1 = (as * dy * dy + bs * dx * dx) * rden * 0.25f;
    float t2 = cs * (x2 - x1) * (y1 - y2) * rden * 0.5f;
    float t3 = 0.5f * __logf(denom * __fdividef(1.f, 4.f * sqrtf(det1 * det2) + eps) + eps);
    float bd = fminf(fmaxf(t1 + t2 + t3, eps), 100.f);
    return sqrtf(1.f - __expf(-bd) + 1e-7f);
}

__device__ __forceinline__ float warpSum(float v) {
    #pragma unroll
    for (int o = 16; o; o >>= 1) v += __shfl_xor_sync(FULLM, v, o);
    return v;
}

__device__ __forceinline__ float focal_bg(float x) {
    float e = __expf(-fabsf(x));
    float den = 1.f + e;
    float rden = __fdividef(1.f, den);
    float p = (x >= 0.f) ? rden : e * rden;
    float bce = fmaxf(x, 0.f) + __logf(den);
    return bce * 0.75f * p * p;
}

// ------------------------------------------------------------------ kernels
// Per-gt precompute + maxAI reset (claim array reset incrementally by the
// previous replay's k_loss_final; zero-state is valid).
__global__ void __launch_bounds__(256) k_init(const float* __restrict__ gbox,
                                              const int*   __restrict__ glab,
                                              const float* __restrict__ vmask) {
    int i = blockIdx.x * 256 + threadIdx.x;
    if (i < Bb * Mm) {
        float gx = gbox[i * 5 + 0], gy = gbox[i * 5 + 1];
        float gw = gbox[i * 5 + 2], gh = gbox[i * 5 + 3], ga = gbox[i * 5 + 4];
        float ca, sa; __sincosf(ga, &sa, &ca);
        float A = gw * gw * (1.f/12.f), B = gh * gh * (1.f/12.f);
        float va = A * ca * ca + B * sa * sa;
        float vb = A * sa * sa + B * ca * ca;
        float vc = (A - B) * ca * sa;
        float det = fmaxf(va * vb - vc * vc, 0.f);
        float r = 0.5f * sqrtf(gw * gw + gh * gh);
        float t = fminf(fmaxf(ga / ANGLE_SCALE_F, 0.f), 89.99f);
        int li = (int)t;
        int ri = min(li + 1, 90);
        float lw = (float)ri - t;
        d_gprep[i * 4 + 0] = make_float4(gx, gy, va, vb);
        d_gprep[i * 4 + 1] = make_float4(vc, det, r, lw);
        d_gprep[i * 4 + 2] = make_float4(ca, sa, gw * 0.5f, gh * 0.5f);
        d_gprep[i * 4 + 3] = make_float4(__int_as_float(li), __int_as_float(glab[i]),
                                         vmask[i], 0.f);
        d_maxAI[i] = make_uint2(0u, 0u);
    }
}

// Warp per 4 anchors, 8 lanes per anchor. Fuses the background focal-BCE
// for this block's 120 float4 of cls.
__global__ void __launch_bounds__(256) k_decode(const float* __restrict__ reg,
                                                const float* __restrict__ ang,
                                                const float4* __restrict__ cls4) {
    __shared__ float sw[8];
    int tid = threadIdx.x;
    int wid = tid >> 5, lane = tid & 31;
    int abase = blockIdx.x * 32 + wid * 4;
    int j = lane >> 3;          // anchor within group
    int s = lane & 7;           // sub-lane within anchor
    int ga = abase + j;
    const float* row = ang + (size_t)ga * Aa;

    float ssum = 0.f, wsum = 0.f;
    float fi = (float)s;
    #pragma unroll
    for (int k = 0; k < 11; k++) {
        float p = __expf(row[s + 8 * k]);
        ssum += p;
        wsum = fmaf(fi, p, wsum);
        fi += 8.f;
    }
    if (s < 3) {
        float p = __expf(row[s + 88]);
        ssum += p;
        wsum = fmaf((float)(s + 88), p, wsum);
    }
    #pragma unroll
    for (int o = 4; o; o >>= 1) {
        ssum += __shfl_xor_sync(FULLM, ssum, o);
        wsum += __shfl_xor_sync(FULLM, wsum, o);
    }

    if (s == 0) {
        float angle = ANGLE_SCALE_F * __fdividef(wsum, ssum);
        float Z = __logf(ssum);
        const float4 rd = ((const float4*)reg)[ga];   // lt=(x,y) rb=(z,w)
        float offx = (rd.z - rd.x) * 0.5f, offy = (rd.w - rd.y) * 0.5f;
        float c, sn; __sincosf(angle, &sn, &c);
        float ox = offx * c - offy * sn;
        float oy = offx * sn + offy * c;
        int n = ga % Nn;
        float ax, ay, st;
        if (n < 16384)      { ax = ((n & 127) + 0.5f) * 8.f;  ay = ((n >> 7) + 0.5f) * 8.f;  st = 8.f;  }
        else if (n < 20480) { int k = n - 16384; ax = ((k & 63) + 0.5f) * 16.f; ay = ((k >> 6) + 0.5f) * 16.f; st = 16.f; }
        else                { int k = n - 20480; ax = ((k & 31) + 0.5f) * 32.f; ay = ((k >> 5) + 0.5f) * 32.f; st = 32.f; }
        float X = ox * st + ax, Y = oy * st + ay;
        float W = (rd.x + rd.z) * st, H = (rd.y + rd.w) * st;
        float A = W * W * (1.f/12.f), B = H * H * (1.f/12.f);
        float va = A * c * c + B * sn * sn;
        float vb = A * sn * sn + B * c * c;
        float vc = (A - B) * c * sn;
        float det = fmaxf(va * vb - vc * vc, 0.f);
        float4* pp = (float4*)(d_pred + (size_t)ga * 8);
        pp[0] = make_float4(X, Y, va, vb);
        pp[1] = make_float4(vc, det, Z, 0.f);
    }

    // fused background focal-BCE: this block's 120 float4 of cls
    float acc = 0.f;
    if (tid < 120) {
        float4 v = cls4[(size_t)blockIdx.x * 120 + tid];
        acc = focal_bg(v.x) + focal_bg(v.y) + focal_bg(v.z) + focal_bg(v.w);
    }
    acc = warpSum(acc);
    if (lane == 0) sw[wid] = acc;
    __syncthreads();
    if (tid == 0) {
        float t = 0.f;
        #pragma unroll
        for (int w = 0; w < 8; w++) t += sw[w];
        atomicAdd(&d_acc[0], t);
    }
}

// One block (128 thr) per (b,m): collect candidates, per-warp exact top-13,
// warp-0 merge. 2 block barriers total.
__global__ void __launch_bounds__(128) k_topk(const float* __restrict__ cls) {
    __shared__ unsigned long long sKey[NC];
    __shared__ unsigned long long sW[52];     // 4 warps x 13 winners
    __shared__ int sCnt;

    int bm = blockIdx.x;
    int b = bm >> 6, m = bm & 63;
    const float4 q0 = d_gprep[bm * 4 + 0];
    const float4 q1 = d_gprep[bm * 4 + 1];
    const float4 q2 = d_gprep[bm * 4 + 2];
    const float4 q3 = d_gprep[bm * 4 + 3];
    if (q3.z == 0.f) return;      // pad gt

    const float gx = q0.x, gy = q0.y, gva = q0.z, gvb = q0.w;
    const float gvc = q1.x, gdet = q1.y, r = q1.z;
    const float ca = q2.x, sa = q2.y, hw = q2.z, hh = q2.w;
    const int lbl = __float_as_int(q3.y);

    int tid = threadIdx.x;
    int wid = tid >> 5, lane = tid & 31;
    if (tid == 0) sCnt = 0;
    if (tid < 52) sW[tid] = 0ull;
    __syncthreads();

    const int   baseL[3] = {0, 16384, 20480};
    const int   ngL[3]   = {128, 64, 32};
    const float sL[3]    = {8.f, 16.f, 32.f};
    #pragma unroll
    for (int L = 0; L < 3; L++) {
        float s = sL[L]; int ng = ngL[L];
        float inv = 1.f / s;
        int ix0 = max(0,      (int)floorf((gx - r) * inv - 0.5f));
        int ix1 = min(ng - 1, (int)ceilf ((gx + r) * inv - 0.5f));
        int iy0 = max(0,      (int)floorf((gy - r) * inv - 0.5f));
        int iy1 = min(ng - 1, (int)ceilf ((gy + r) * inv - 0.5f));
        if (ix1 < ix0 || iy1 < iy0) continue;
        int W = ix1 - ix0 + 1;
        int tot = W * (iy1 - iy0 + 1);
        for (int t0 = 0; t0 < tot; t0 += 128) {
            int t = t0 + tid;
            bool act = false;
            unsigned long long key = 0ull;
            if (t < tot) {
                int q = t / W;
                int ix = ix0 + (t - q * W);
                int iy = iy0 + q;
                float ax = (ix + 0.5f) * s, ay = (iy + 0.5f) * s;
                float dx = ax - gx, dy = ay - gy;
                float xr = dx * ca + dy * sa;
                float yr = -dx * sa + dy * ca;
                if (fabsf(xr) < hw && fabsf(yr) < hh) {
                    int n = baseL[L] + iy * ng + ix;
                    int gi = b * Nn + n;
                    const float4* pp = (const float4*)(d_pred + (size_t)gi * 8);
                    float4 p0 = pp[0], p1 = pp[1];
                    float hd = probiou_pre(gx, gy, gva, gvb, gvc, gdet,
                                           p0.x, p0.y, p0.z, p0.w, p1.x, p1.y);
                    float iou = fmaxf(1.f - hd, 0.f);
                    float x = cls[(size_t)gi * Cc + lbl];
                    float sg = __fdividef(1.f, 1.f + __expf(-x));
                    float i2 = iou * iou;
                    float al = sg * i2 * i2 * i2;
                    if (al > 1e-9f) {
                        act = true;
                        key = ((unsigned long long)__float_as_uint(al) << 32)
                            | (unsigned)(0x7fffffff - n);
                    }
                }
            }
            unsigned mask = __ballot_sync(FULLM, act);
            if (mask) {
                int base = 0;
                if (lane == 0) base = atomicAdd(&sCnt, __popc(mask));
                base = __shfl_sync(FULLM, base, 0);
                if (act) {
                    int off = base + __popc(mask & ((1u << lane) - 1u));
                    if (off < NC) sKey[off] = key;
                }
            }
        }
    }
    __syncthreads();
    int cnt = min(sCnt, NC);

    // per-warp exact top-13 over its strided quarter (sync-free)
    #pragma unroll 1
    for (int k = 0; k < KTOP; k++) {
        unsigned long long best = 0ull; int bs = -1;
        for (int s = wid * 32 + lane; s < cnt; s += 128) {
            unsigned long long v = sKey[s];
            if (v > best) { best = v; bs = s; }
        }
        #pragma unroll
        for (int o = 16; o; o >>= 1) {
            unsigned long long ov = __shfl_xor_sync(FULLM, best, o);
            int os = __shfl_xor_sync(FULLM, bs, o);
            if (ov > best) { best = ov; bs = os; }
        }
        if (best == 0ull) break;
        if (lane == 0) { sW[wid * KTOP + k] = best; sKey[bs] = 0ull; }
    }
    __syncthreads();

    // warp 0 merges the 52 warp-winners; round-k winner in lane k's register
    if (wid == 0) {
        unsigned long long v0 = (lane < 52) ? sW[lane] : 0ull;
        unsigned long long v1 = (lane + 32 < 52) ? sW[lane + 32] : 0ull;
        unsigned long long mykey = 0ull;
        int nfin = 0;
        #pragma unroll 1
        for (int k = 0; k < KTOP; k++) {
            unsigned long long best = (v0 > v1) ? v0 : v1;
            #pragma unroll
            for (int o = 16; o; o >>= 1) {
                unsigned long long ov = __shfl_xor_sync(FULLM, best, o);
                if (ov > best) best = ov;
            }
            if (best == 0ull) break;
            if (v0 == best) v0 = 0ull;
            if (v1 == best) v1 = 0ull;
            if (lane == k) mykey = best;
            nfin++;
        }
        if (nfin) {
            int base = 0;
            if (lane == 0) base = atomicAdd(&d_listcnt, nfin);
            base = __shfl_sync(FULLM, base, 0);
            if (lane < nfin) {
                int n = 0x7fffffff - (int)(mykey & 0xffffffffu);
                float al = __uint_as_float((unsigned)(mykey >> 32));
                int gi = b * Nn + n;
                atomicAdd(&d_claim[gi].x, 1);
                atomicMax(&d_claim[gi].y, 0x7fffffff - m);
                const float4* pp = (const float4*)(d_pred + (size_t)gi * 8);
                float4 p0 = pp[0], p1 = pp[1];
                float hd = probiou_pre(gx, gy, gva, gvb, gvc, gdet,
                                       p0.x, p0.y, p0.z, p0.w, p1.x, p1.y);
                d_rec[base + lane] = make_float4(__int_as_float(gi), __int_as_float(m),
                                                 al, hd);
            }
        }
    }
}

// One thread per record: election, warp-cooperative multi-claim argmax,
// angle-CE + npos, maxAI atomics, elected append. NO serial tail.
__global__ void __launch_bounds__(256) k_resolve(const float* __restrict__ cls,
                                                 const float* __restrict__ ang) {
    int tid = threadIdx.x;
    int idx = blockIdx.x * 256 + tid;
    int lane = tid & 31;
    int lc = d_listcnt;
    bool has = idx < lc;
    float4 rec = has ? d_rec[idx] : make_float4(0.f, 0.f, 0.f, 0.f);
    int gi = __float_as_int(rec.x);
    int m  = __float_as_int(rec.y);
    float align = rec.z, hd = rec.w;
    int2 cl = has ? d_claim[gi] : make_int2(0, 0);
    bool elected = has && (cl.y == 0x7fffffff - m);
    bool multi = elected && (cl.x > 1);
    int b = gi / Nn;
    int tgt = m;

    unsigned mb = __ballot_sync(FULLM, multi);
    while (mb) {
        int src = __ffs(mb) - 1; mb &= mb - 1;
        int sgi = __shfl_sync(FULLM, gi, src);
        int sb = sgi / Nn;
        const float4* pp = (const float4*)(d_pred + (size_t)sgi * 8);
        float4 p0 = pp[0], p1 = pp[1];
        float bi = -1.f, bh = 0.f; int bmm = 0;
        #pragma unroll
        for (int j = 0; j < 2; j++) {
            int mm = lane + j * 32;
            float4 g0 = d_gprep[(sb * Mm + mm) * 4 + 0];
            float4 g1 = d_gprep[(sb * Mm + mm) * 4 + 1];
            float h = probiou_pre(g0.x, g0.y, g0.z, g0.w, g1.x, g1.y,
                                  p0.x, p0.y, p0.z, p0.w, p1.x, p1.y);
            float io = fmaxf(1.f - h, 0.f);
            if (io > bi) { bi = io; bh = h; bmm = mm; }
        }
        #pragma unroll
        for (int o = 16; o; o >>= 1) {
            float ov = __shfl_xor_sync(FULLM, bi, o);
            float oh = __shfl_xor_sync(FULLM, bh, o);
            int   om = __shfl_xor_sync(FULLM, bmm, o);
            if (ov > bi || (ov == bi && om < bmm)) { bi = ov; bh = oh; bmm = om; }
        }
        if (lane == src) {
            tgt = bmm; hd = bh;
            int lbl = __float_as_int(d_gprep[(sb * Mm + tgt) * 4 + 3].y);
            float x = cls[(size_t)sgi * Cc + lbl];
            float sg = __fdividef(1.f, 1.f + __expf(-x));
            float i2 = bi * bi;
            align = sg * i2 * i2 * i2;
        }
    }

    float c3 = 0.f, c4 = 0.f;
    int ebm = 0;
    if (elected) {
        ebm = b * Mm + tgt;
        atomicMax(&d_maxAI[ebm].x, __float_as_uint(align));
        atomicMax(&d_maxAI[ebm].y, __float_as_uint(fmaxf(1.f - hd, 0.f)));
        float4 g1 = d_gprep[ebm * 4 + 1];
        float4 g3 = d_gprep[ebm * 4 + 3];
        float lw = g1.w;
        int li = __float_as_int(g3.x);
        int ri = min(li + 1, 90);
        float Z = d_pred[(size_t)gi * 8 + 6];
        const float* xr = ang + (size_t)gi * Aa;
        c3 = (Z - __ldg(xr + li)) * lw + (Z - __ldg(xr + ri)) * (1.f - lw);
        c4 = 1.f;
    }

    // warp-aggregated append of elected entries {gi, bm, align, hd}
    unsigned eb = __ballot_sync(FULLM, elected);
    if (eb) {
        int leader = __ffs(eb) - 1;
        int base = 0;
        if (lane == leader) base = atomicAdd(&d_ecount, __popc(eb));
        base = __shfl_sync(FULLM, base, leader);
        if (elected) {
            int off = __popc(eb & ((1u << lane) - 1u));
            d_e[base + off] = make_float4(__int_as_float(gi), __int_as_float(ebm),
                                          align, hd);
        }
    }
    c3 = warpSum(c3); c4 = warpSum(c4);
    if (lane == 0) { atomicAdd(&d_acc[3], c3); atomicAdd(&d_acc[4], c4); }
}

// One thread per elected entry (cls correction + score_sum + box) and one
// claim-reset slot — fully parallel, single iteration per thread. The
// done-counter last block only does the final scalar arithmetic + resets.
__global__ void __launch_bounds__(256) k_loss_final(const float* __restrict__ cls,
                                                    float* __restrict__ out, int osz) {
    __shared__ bool isLast;
    int tid = threadIdx.x;
    int idx = blockIdx.x * 256 + tid;
    int lane = tid & 31;
    int ec = d_ecount;
    int lc = d_listcnt;

    float c0 = 0.f, c1 = 0.f, c2 = 0.f;
    if (idx < ec) {
        float4 en = d_e[idx];
        int egi = __float_as_int(en.x);
        int bm2 = __float_as_int(en.y);
        float al = en.z, h = en.w;
        uint2 mx = d_maxAI[bm2];
        float na = al * __uint_as_float(mx.y) *
                   __fdividef(1.f, __uint_as_float(mx.x) + 1e-9f);
        int lbl = __float_as_int(d_gprep[bm2 * 4 + 3].y);
        float x = cls[(size_t)egi * Cc + lbl];
        float ex = __expf(-fabsf(x));
        float den = 1.f + ex;
        float rden = __fdividef(1.f, den);
        float p = (x >= 0.f) ? rden : ex * rden;
        float bce0 = fmaxf(x, 0.f) + __logf(den);
        c0 = (bce0 - x * na) * na - bce0 * 0.75f * p * p;
        c1 = na;
        c2 = h * na;
    }
    // distributed claim reset for next replay (duplicates idempotent; safe
    // because no kernel after this reads d_claim until next replay's topk)
    if (idx < lc) {
        int rgi = __float_as_int(d_rec[idx].x);
        d_claim[rgi] = make_int2(0, 0);
    }

    c0 = warpSum(c0); c1 = warpSum(c1); c2 = warpSum(c2);
    if (lane == 0) {
        atomicAdd(&d_acc[0], c0); atomicAdd(&d_acc[1], c1); atomicAdd(&d_acc[2], c2);
    }

    __syncthreads();
    if (tid == 0) {
        __threadfence();
        unsigned prev = atomicAdd(&d_done, 1u);
        isLast = (prev == gridDim.x - 1);
    }
    __syncthreads();
    if (!isLast) return;
    if (tid == 0) {
        __threadfence();
        float clsn = d_acc[0];
        float ss   = fmaxf(d_acc[1], 1.f);
        float boxn = d_acc[2];
        float angn = d_acc[3];
        float npos = fmaxf(d_acc[4], 1.f);
        float lcv = clsn / ss;
        float lbv = boxn / ss;
        float lav = angn / npos;
        float tot = lcv + 2.5f * lbv + 0.05f * lav;
        if (osz >= 4) { out[0] = tot; out[1] = lcv; out[2] = lbv; out[3] = lav; }
        else if (osz >= 1) out[0] = tot;
        // reset scalars for next replay
        #pragma unroll
        for (int i2 = 0; i2 < 8; i2++) d_acc[i2] = 0.f;
        d_listcnt = 0; d_ecount = 0;
        __threadfence();
        d_done = 0u;
    }
}

// ------------------------------------------------------------------ launch
extern "C" void kernel_launch(void* const* d_in, const int* in_sizes, int n_in,
                              void* d_out, int out_size) {
    const float* cls   = (const float*)d_in[0];   // (B,N,C)
    const float* reg   = (const float*)d_in[1];   // (B,N,4)
    const float* ang   = (const float*)d_in[2];   // (B,N,91)
    const int*   glab  = (const int*)  d_in[3];   // (B,M,1)
    const float* gbox  = (const float*)d_in[4];   // (B,M,5)
    const float* vmask = (const float*)d_in[5];   // (B,M,1)
    float* out = (float*)d_out;

    k_init      <<<4, 256>>>(gbox, glab, vmask);                        // idx 0
    k_decode    <<<NTOT / 32, 256>>>(reg, ang, (const float4*)cls);     // idx 1
    k_topk      <<<Bb * Mm, 128>>>(cls);                                // idx 2
    k_resolve   <<<NREC / 256, 256>>>(cls, ang);                        // idx 3 (ncu capture)
    k_loss_final<<<NREC / 256, 256>>>(cls, out, out_size);              // idx 4
}

// round 10
// speedup vs baseline: 1.5432x; 1.0856x over previous
#include <cuda_runtime.h>
#include <math.h>

// Problem constants (fixed by setup_inputs)
#define Bb 16
#define Mm 64
#define Nn 21504          // 128^2 + 64^2 + 32^2
#define Cc 15
#define Aa 91             // ANGLE_BINS + 1
#define KTOP 13
#define NTOT (Bb*Nn)      // 344064
#define NREC (Bb*Mm*KTOP) // 13312
#define NC 736            // max in-box candidates
#define ANGLE_SCALE_F 0.017453292519943295f  // pi/2/90
#define FULLM 0xffffffffu

// ------------------------------------------------------------------ scratch
__device__ float    d_pred[(size_t)NTOT*8];   // {x,y,va,vb},{vc,det,Z,0}
__device__ int2     d_claim[NTOT];            // .x = cnt, .y = max(INT_MAX-m); 0 = unclaimed
__device__ float4   d_gprep[Bb*Mm*4];         // q0{gx,gy,va,vb} q1{vc,det,r,lw} q2{ca,sa,hw,hh} q3{li,lbl,vmask,-}
__device__ uint2    d_maxAI[Bb*Mm];           // .x = max align bits, .y = max iou bits
__device__ float    d_acc[8];                 // 0 cls, 1 score_sum, 2 box, 3 angle, 4 npos
__device__ int      d_listcnt;
__device__ float4   d_rec[NREC];              // {gi, m, align, hd}
__device__ float4   d_e[NREC];                // {gi, bm(-1=invalid), align, hd} per record
__device__ unsigned d_done;

// ------------------------------------------------------------------ helpers
__device__ __forceinline__ float probiou_pre(
    float x1, float y1, float a1, float b1, float c1, float det1,
    float x2, float y2, float a2, float b2, float c2, float det2) {
    const float eps = 1e-3f;
    float as = a1 + a2, bs = b1 + b2, cs = c1 + c2;
    float dx = x1 - x2, dy = y1 - y2;
    float denom = as * bs - cs * cs + eps;
    float rden = __fdividef(1.f, denom);
    float t1 = (as * dy * dy + bs * dx * dx) * rden * 0.25f;
    float t2 = cs * (x2 - x1) * (y1 - y2) * rden * 0.5f;
    float t3 = 0.5f * __logf(denom * __fdividef(1.f, 4.f * sqrtf(det1 * det2) + eps) + eps);
    float bd = fminf(fmaxf(t1 + t2 + t3, eps), 100.f);
    return sqrtf(1.f - __expf(-bd) + 1e-7f);
}

__device__ __forceinline__ float warpSum(float v) {
    #pragma unroll
    for (int o = 16; o; o >>= 1) v += __shfl_xor_sync(FULLM, v, o);
    return v;
}

__device__ __forceinline__ float focal_bg(float x) {
    float e = __expf(-fabsf(x));
    float den = 1.f + e;
    float rden = __fdividef(1.f, den);
    float p = (x >= 0.f) ? rden : e * rden;
    float bce = fmaxf(x, 0.f) + __logf(den);
    return bce * 0.75f * p * p;
}

// ------------------------------------------------------------------ kernels
// Per-gt precompute + maxAI reset (claim array reset incrementally by the
// previous replay's k_loss_final; zero-state is valid).
__global__ void __launch_bounds__(256) k_init(const float* __restrict__ gbox,
                                              const int*   __restrict__ glab,
                                              const float* __restrict__ vmask) {
    int i = blockIdx.x * 256 + threadIdx.x;
    if (i < Bb * Mm) {
        float gx = gbox[i * 5 + 0], gy = gbox[i * 5 + 1];
        float gw = gbox[i * 5 + 2], gh = gbox[i * 5 + 3], ga = gbox[i * 5 + 4];
        float ca, sa; __sincosf(ga, &sa, &ca);
        float A = gw * gw * (1.f/12.f), B = gh * gh * (1.f/12.f);
        float va = A * ca * ca + B * sa * sa;
        float vb = A * sa * sa + B * ca * ca;
        float vc = (A - B) * ca * sa;
        float det = fmaxf(va * vb - vc * vc, 0.f);
        float r = 0.5f * sqrtf(gw * gw + gh * gh);
        float t = fminf(fmaxf(ga / ANGLE_SCALE_F, 0.f), 89.99f);
        int li = (int)t;
        int ri = min(li + 1, 90);
        float lw = (float)ri - t;
        d_gprep[i * 4 + 0] = make_float4(gx, gy, va, vb);
        d_gprep[i * 4 + 1] = make_float4(vc, det, r, lw);
        d_gprep[i * 4 + 2] = make_float4(ca, sa, gw * 0.5f, gh * 0.5f);
        d_gprep[i * 4 + 3] = make_float4(__int_as_float(li), __int_as_float(glab[i]),
                                         vmask[i], 0.f);
        d_maxAI[i] = make_uint2(0u, 0u);
    }
}

// Warp per 4 anchors, 8 lanes per anchor. Fuses the background focal-BCE
// for this block's 120 float4 of cls.
__global__ void __launch_bounds__(256) k_decode(const float* __restrict__ reg,
                                                const float* __restrict__ ang,
                                                const float4* __restrict__ cls4) {
    __shared__ float sw[8];
    int tid = threadIdx.x;
    int wid = tid >> 5, lane = tid & 31;
    int abase = blockIdx.x * 32 + wid * 4;
    int j = lane >> 3;          // anchor within group
    int s = lane & 7;           // sub-lane within anchor
    int ga = abase + j;
    const float* row = ang + (size_t)ga * Aa;

    float ssum = 0.f, wsum = 0.f;
    float fi = (float)s;
    #pragma unroll
    for (int k = 0; k < 11; k++) {
        float p = __expf(row[s + 8 * k]);
        ssum += p;
        wsum = fmaf(fi, p, wsum);
        fi += 8.f;
    }
    if (s < 3) {
        float p = __expf(row[s + 88]);
        ssum += p;
        wsum = fmaf((float)(s + 88), p, wsum);
    }
    #pragma unroll
    for (int o = 4; o; o >>= 1) {
        ssum += __shfl_xor_sync(FULLM, ssum, o);
        wsum += __shfl_xor_sync(FULLM, wsum, o);
    }

    if (s == 0) {
        float angle = ANGLE_SCALE_F * __fdividef(wsum, ssum);
        float Z = __logf(ssum);
        const float4 rd = ((const float4*)reg)[ga];   // lt=(x,y) rb=(z,w)
        float offx = (rd.z - rd.x) * 0.5f, offy = (rd.w - rd.y) * 0.5f;
        float c, sn; __sincosf(angle, &sn, &c);
        float ox = offx * c - offy * sn;
        float oy = offx * sn + offy * c;
        int n = ga % Nn;
        float ax, ay, st;
        if (n < 16384)      { ax = ((n & 127) + 0.5f) * 8.f;  ay = ((n >> 7) + 0.5f) * 8.f;  st = 8.f;  }
        else if (n < 20480) { int k = n - 16384; ax = ((k & 63) + 0.5f) * 16.f; ay = ((k >> 6) + 0.5f) * 16.f; st = 16.f; }
        else                { int k = n - 20480; ax = ((k & 31) + 0.5f) * 32.f; ay = ((k >> 5) + 0.5f) * 32.f; st = 32.f; }
        float X = ox * st + ax, Y = oy * st + ay;
        float W = (rd.x + rd.z) * st, H = (rd.y + rd.w) * st;
        float A = W * W * (1.f/12.f), B = H * H * (1.f/12.f);
        float va = A * c * c + B * sn * sn;
        float vb = A * sn * sn + B * c * c;
        float vc = (A - B) * c * sn;
        float det = fmaxf(va * vb - vc * vc, 0.f);
        float4* pp = (float4*)(d_pred + (size_t)ga * 8);
        pp[0] = make_float4(X, Y, va, vb);
        pp[1] = make_float4(vc, det, Z, 0.f);
    }

    // fused background focal-BCE: this block's 120 float4 of cls
    float acc = 0.f;
    if (tid < 120) {
        float4 v = cls4[(size_t)blockIdx.x * 120 + tid];
        acc = focal_bg(v.x) + focal_bg(v.y) + focal_bg(v.z) + focal_bg(v.w);
    }
    acc = warpSum(acc);
    if (lane == 0) sw[wid] = acc;
    __syncthreads();
    if (tid == 0) {
        float t = 0.f;
        #pragma unroll
        for (int w = 0; w < 8; w++) t += sw[w];
        atomicAdd(&d_acc[0], t);
    }
}

// One block (128 thr) per (b,m): collect candidates, per-warp exact top-13,
// warp-0 merge. 2 block barriers total.
__global__ void __launch_bounds__(128) k_topk(const float* __restrict__ cls) {
    __shared__ unsigned long long sKey[NC];
    __shared__ unsigned long long sW[52];     // 4 warps x 13 winners
    __shared__ int sCnt;

    int bm = blockIdx.x;
    int b = bm >> 6, m = bm & 63;
    const float4 q0 = d_gprep[bm * 4 + 0];
    const float4 q1 = d_gprep[bm * 4 + 1];
    const float4 q2 = d_gprep[bm * 4 + 2];
    const float4 q3 = d_gprep[bm * 4 + 3];
    if (q3.z == 0.f) return;      // pad gt

    const float gx = q0.x, gy = q0.y, gva = q0.z, gvb = q0.w;
    const float gvc = q1.x, gdet = q1.y, r = q1.z;
    const float ca = q2.x, sa = q2.y, hw = q2.z, hh = q2.w;
    const int lbl = __float_as_int(q3.y);

    int tid = threadIdx.x;
    int wid = tid >> 5, lane = tid & 31;
    if (tid == 0) sCnt = 0;
    if (tid < 52) sW[tid] = 0ull;
    __syncthreads();

    const int   baseL[3] = {0, 16384, 20480};
    const int   ngL[3]   = {128, 64, 32};
    const float sL[3]    = {8.f, 16.f, 32.f};
    #pragma unroll
    for (int L = 0; L < 3; L++) {
        float s = sL[L]; int ng = ngL[L];
        float inv = 1.f / s;
        int ix0 = max(0,      (int)floorf((gx - r) * inv - 0.5f));
        int ix1 = min(ng - 1, (int)ceilf ((gx + r) * inv - 0.5f));
        int iy0 = max(0,      (int)floorf((gy - r) * inv - 0.5f));
        int iy1 = min(ng - 1, (int)ceilf ((gy + r) * inv - 0.5f));
        if (ix1 < ix0 || iy1 < iy0) continue;
        int W = ix1 - ix0 + 1;
        int tot = W * (iy1 - iy0 + 1);
        for (int t0 = 0; t0 < tot; t0 += 128) {
            int t = t0 + tid;
            bool act = false;
            unsigned long long key = 0ull;
            if (t < tot) {
                int q = t / W;
                int ix = ix0 + (t - q * W);
                int iy = iy0 + q;
                float ax = (ix + 0.5f) * s, ay = (iy + 0.5f) * s;
                float dx = ax - gx, dy = ay - gy;
                float xr = dx * ca + dy * sa;
                float yr = -dx * sa + dy * ca;
                if (fabsf(xr) < hw && fabsf(yr) < hh) {
                    int n = baseL[L] + iy * ng + ix;
                    int gi = b * Nn + n;
                    const float4* pp = (const float4*)(d_pred + (size_t)gi * 8);
                    float4 p0 = pp[0], p1 = pp[1];
                    float hd = probiou_pre(gx, gy, gva, gvb, gvc, gdet,
                                           p0.x, p0.y, p0.z, p0.w, p1.x, p1.y);
                    float iou = fmaxf(1.f - hd, 0.f);
                    float x = cls[(size_t)gi * Cc + lbl];
                    float sg = __fdividef(1.f, 1.f + __expf(-x));
                    float i2 = iou * iou;
                    float al = sg * i2 * i2 * i2;
                    if (al > 1e-9f) {
                        act = true;
                        key = ((unsigned long long)__float_as_uint(al) << 32)
                            | (unsigned)(0x7fffffff - n);
                    }
                }
            }
            unsigned mask = __ballot_sync(FULLM, act);
            if (mask) {
                int base = 0;
                if (lane == 0) base = atomicAdd(&sCnt, __popc(mask));
                base = __shfl_sync(FULLM, base, 0);
                if (act) {
                    int off = base + __popc(mask & ((1u << lane) - 1u));
                    if (off < NC) sKey[off] = key;
                }
            }
        }
    }
    __syncthreads();
    int cnt = min(sCnt, NC);

    // per-warp exact top-13 over its strided quarter (sync-free)
    #pragma unroll 1
    for (int k = 0; k < KTOP; k++) {
        unsigned long long best = 0ull; int bs = -1;
        for (int s = wid * 32 + lane; s < cnt; s += 128) {
            unsigned long long v = sKey[s];
            if (v > best) { best = v; bs = s; }
        }
        #pragma unroll
        for (int o = 16; o; o >>= 1) {
            unsigned long long ov = __shfl_xor_sync(FULLM, best, o);
            int os = __shfl_xor_sync(FULLM, bs, o);
            if (ov > best) { best = ov; bs = os; }
        }
        if (best == 0ull) break;
        if (lane == 0) { sW[wid * KTOP + k] = best; sKey[bs] = 0ull; }
    }
    __syncthreads();

    // warp 0 merges the 52 warp-winners; round-k winner in lane k's register
    if (wid == 0) {
        unsigned long long v0 = (lane < 52) ? sW[lane] : 0ull;
        unsigned long long v1 = (lane + 32 < 52) ? sW[lane + 32] : 0ull;
        unsigned long long mykey = 0ull;
        int nfin = 0;
        #pragma unroll 1
        for (int k = 0; k < KTOP; k++) {
            unsigned long long best = (v0 > v1) ? v0 : v1;
            #pragma unroll
            for (int o = 16; o; o >>= 1) {
                unsigned long long ov = __shfl_xor_sync(FULLM, best, o);
                if (ov > best) best = ov;
            }
            if (best == 0ull) break;
            if (v0 == best) v0 = 0ull;
            if (v1 == best) v1 = 0ull;
            if (lane == k) mykey = best;
            nfin++;
        }
        if (nfin) {
            int base = 0;
            if (lane == 0) base = atomicAdd(&d_listcnt, nfin);
            base = __shfl_sync(FULLM, base, 0);
            if (lane < nfin) {
                int n = 0x7fffffff - (int)(mykey & 0xffffffffu);
                float al = __uint_as_float((unsigned)(mykey >> 32));
                int gi = b * Nn + n;
                atomicAdd(&d_claim[gi].x, 1);
                atomicMax(&d_claim[gi].y, 0x7fffffff - m);
                const float4* pp = (const float4*)(d_pred + (size_t)gi * 8);
                float4 p0 = pp[0], p1 = pp[1];
                float hd = probiou_pre(gx, gy, gva, gvb, gvc, gdet,
                                       p0.x, p0.y, p0.z, p0.w, p1.x, p1.y);
                d_rec[base + lane] = make_float4(__int_as_float(gi), __int_as_float(m),
                                                 al, hd);
            }
        }
    }
}

// ONE WARP PER RECORD (8 records/block, grid = NREC/8): election,
// lane-parallel 64-gt argmax for multi-claimed anchors, angle-CE + npos,
// maxAI atomics, flagged write to d_e[record].
__global__ void __launch_bounds__(256) k_resolve(const float* __restrict__ cls,
                                                 const float* __restrict__ ang) {
    __shared__ float sc3, sc4;
    int tid = threadIdx.x;
    int wid = tid >> 5, lane = tid & 31;
    if (tid == 0) { sc3 = 0.f; sc4 = 0.f; }
    __syncthreads();

    int wrec = blockIdx.x * 8 + wid;
    int lc = d_listcnt;
    if (wrec < lc) {
        float4 rec = d_rec[wrec];                    // uniform across warp
        int gi = __float_as_int(rec.x);
        int m  = __float_as_int(rec.y);
        float align = rec.z, hd = rec.w;
        int2 cl = d_claim[gi];                       // uniform
        bool elected = (cl.y == 0x7fffffff - m);
        int b = gi / Nn;
        int tgt = m;
        if (elected) {
            if (cl.x > 1) {
                // lane-parallel argmax over all 64 gts (2 per lane)
                const float4* pp = (const float4*)(d_pred + (size_t)gi * 8);
                float4 p0 = pp[0], p1 = pp[1];
                float bi = -1.f, bh = 0.f; int bmm = 0;
                #pragma unroll
                for (int j = 0; j < 2; j++) {
                    int mm = lane + j * 32;
                    float4 g0 = d_gprep[(b * Mm + mm) * 4 + 0];
                    float4 g1 = d_gprep[(b * Mm + mm) * 4 + 1];
                    float h = probiou_pre(g0.x, g0.y, g0.z, g0.w, g1.x, g1.y,
                                          p0.x, p0.y, p0.z, p0.w, p1.x, p1.y);
                    float io = fmaxf(1.f - h, 0.f);
                    if (io > bi) { bi = io; bh = h; bmm = mm; }
                }
                #pragma unroll
                for (int o = 16; o; o >>= 1) {
                    float ov = __shfl_xor_sync(FULLM, bi, o);
                    float oh = __shfl_xor_sync(FULLM, bh, o);
                    int   om = __shfl_xor_sync(FULLM, bmm, o);
                    if (ov > bi || (ov == bi && om < bmm)) { bi = ov; bh = oh; bmm = om; }
                }
                tgt = bmm; hd = bh;
                int lbl = __float_as_int(d_gprep[(b * Mm + tgt) * 4 + 3].y);
                float x = cls[(size_t)gi * Cc + lbl];    // same addr all lanes
                float sg = __fdividef(1.f, 1.f + __expf(-x));
                float i2 = bi * bi;
                align = sg * i2 * i2 * i2;
            }
            if (lane == 0) {
                int ebm = b * Mm + tgt;
                atomicMax(&d_maxAI[ebm].x, __float_as_uint(align));
                atomicMax(&d_maxAI[ebm].y, __float_as_uint(fmaxf(1.f - hd, 0.f)));
                float4 g1 = d_gprep[ebm * 4 + 1];
                float4 g3 = d_gprep[ebm * 4 + 3];
                float lw = g1.w;
                int li = __float_as_int(g3.x);
                int ri = min(li + 1, 90);
                float Z = d_pred[(size_t)gi * 8 + 6];
                const float* xr = ang + (size_t)gi * Aa;
                float c3 = (Z - __ldg(xr + li)) * lw + (Z - __ldg(xr + ri)) * (1.f - lw);
                atomicAdd(&sc3, c3);
                atomicAdd(&sc4, 1.f);
                d_e[wrec] = make_float4(__int_as_float(gi), __int_as_float(ebm),
                                        align, hd);
            }
        } else if (lane == 0) {
            d_e[wrec] = make_float4(0.f, __int_as_float(-1), 0.f, 0.f);
        }
    }
    __syncthreads();
    if (tid == 0 && (sc3 != 0.f || sc4 != 0.f)) {
        atomicAdd(&d_acc[3], sc3);
        atomicAdd(&d_acc[4], sc4);
    }
}

// One thread per record slot: flagged loss terms + claim reset; last block
// finalizes output and resets scalars.
__global__ void __launch_bounds__(128) k_loss_final(const float* __restrict__ cls,
                                                    float* __restrict__ out, int osz) {
    __shared__ bool isLast;
    int tid = threadIdx.x;
    int idx = blockIdx.x * 128 + tid;
    int lane = tid & 31;
    int lc = d_listcnt;

    float c0 = 0.f, c1 = 0.f, c2 = 0.f;
    if (idx < lc) {
        float4 en = d_e[idx];
        int bm2 = __float_as_int(en.y);
        if (bm2 >= 0) {
            int egi = __float_as_int(en.x);
            float al = en.z, h = en.w;
            uint2 mx = d_maxAI[bm2];
            float na = al * __uint_as_float(mx.y) *
                       __fdividef(1.f, __uint_as_float(mx.x) + 1e-9f);
            int lbl = __float_as_int(d_gprep[bm2 * 4 + 3].y);
            float x = cls[(size_t)egi * Cc + lbl];
            float ex = __expf(-fabsf(x));
            float den = 1.f + ex;
            float rden = __fdividef(1.f, den);
            float p = (x >= 0.f) ? rden : ex * rden;
            float bce0 = fmaxf(x, 0.f) + __logf(den);
            c0 = (bce0 - x * na) * na - bce0 * 0.75f * p * p;
            c1 = na;
            c2 = h * na;
        }
        // distributed claim reset for next replay (duplicates idempotent)
        int rgi = __float_as_int(d_rec[idx].x);
        d_claim[rgi] = make_int2(0, 0);
    }

    c0 = warpSum(c0); c1 = warpSum(c1); c2 = warpSum(c2);
    if (lane == 0) {
        atomicAdd(&d_acc[0], c0); atomicAdd(&d_acc[1], c1); atomicAdd(&d_acc[2], c2);
    }

    __syncthreads();
    if (tid == 0) {
        __threadfence();
        unsigned prev = atomicAdd(&d_done, 1u);
        isLast = (prev == gridDim.x - 1);
    }
    __syncthreads();
    if (!isLast) return;
    if (tid == 0) {
        __threadfence();
        float clsn = d_acc[0];
        float ss   = fmaxf(d_acc[1], 1.f);
        float boxn = d_acc[2];
        float angn = d_acc[3];
        float npos = fmaxf(d_acc[4], 1.f);
        float lcv = clsn / ss;
        float lbv = boxn / ss;
        float lav = angn / npos;
        float tot = lcv + 2.5f * lbv + 0.05f * lav;
        if (osz >= 4) { out[0] = tot; out[1] = lcv; out[2] = lbv; out[3] = lav; }
        else if (osz >= 1) out[0] = tot;
        // reset scalars for next replay
        #pragma unroll
        for (int i2 = 0; i2 < 8; i2++) d_acc[i2] = 0.f;
        d_listcnt = 0;
        __threadfence();
        d_done = 0u;
    }
}

// ------------------------------------------------------------------ launch
extern "C" void kernel_launch(void* const* d_in, const int* in_sizes, int n_in,
                              void* d_out, int out_size) {
    const float* cls   = (const float*)d_in[0];   // (B,N,C)
    const float* reg   = (const float*)d_in[1];   // (B,N,4)
    const float* ang   = (const float*)d_in[2];   // (B,N,91)
    const int*   glab  = (const int*)  d_in[3];   // (B,M,1)
    const float* gbox  = (const float*)d_in[4];   // (B,M,5)
    const float* vmask = (const float*)d_in[5];   // (B,M,1)
    float* out = (float*)d_out;

    k_init      <<<4, 256>>>(gbox, glab, vmask);                        // idx 0
    k_decode    <<<NTOT / 32, 256>>>(reg, ang, (const float4*)cls);     // idx 1
    k_topk      <<<Bb * Mm, 128>>>(cls);                                // idx 2
    k_resolve   <<<NREC / 8, 256>>>(cls, ang);                          // idx 3 (ncu capture)
    k_loss_final<<<NREC / 128, 128>>>(cls, out, out_size);              // idx 4
}

// round 11
// speedup vs baseline: 1.5529x; 1.0062x over previous
#include <cuda_runtime.h>
#include <math.h>

// Problem constants (fixed by setup_inputs)
#define Bb 16
#define Mm 64
#define Nn 21504          // 128^2 + 64^2 + 32^2
#define Cc 15
#define Aa 91             // ANGLE_BINS + 1
#define KTOP 13
#define NTOT (Bb*Nn)      // 344064
#define NREC (Bb*Mm*KTOP) // 13312
#define NC 736            // max in-box candidates
#define NF4 (NTOT*Cc/4)   // 1290240 float4 of cls
#define ANGLE_SCALE_F 0.017453292519943295f  // pi/2/90
#define FULLM 0xffffffffu

// ------------------------------------------------------------------ scratch
__device__ float    d_pred[(size_t)NTOT*8];   // {x,y,va,vb},{vc,det,Z,0}
__device__ int2     d_claim[NTOT];            // .x = cnt, .y = max(INT_MAX-m); 0 = unclaimed
__device__ float4   d_gprep[Bb*Mm*4];         // q0{gx,gy,va,vb} q1{vc,det,r,lw} q2{ca,sa,hw,hh} q3{li,lbl,vmask,-}
__device__ uint2    d_maxAI[Bb*Mm];           // .x = max align bits, .y = max iou bits
__device__ float    d_acc[8];                 // 0 cls, 1 score_sum, 2 box, 3 angle, 4 npos
__device__ int      d_listcnt;
__device__ float4   d_rec[NREC];              // {gi, m, align, hd}
__device__ float4   d_e[NREC];                // {gi, bm(-1=invalid), align, hd} per record
__device__ unsigned d_done;

// ------------------------------------------------------------------ helpers
__device__ __forceinline__ float probiou_pre(
    float x1, float y1, float a1, float b1, float c1, float det1,
    float x2, float y2, float a2, float b2, float c2, float det2) {
    const float eps = 1e-3f;
    float as = a1 + a2, bs = b1 + b2, cs = c1 + c2;
    float dx = x1 - x2, dy = y1 - y2;
    float denom = as * bs - cs * cs + eps;
    float rden = __fdividef(1.f, denom);
    float t1 = (as * dy * dy + bs * dx * dx) * rden * 0.25f;
    float t2 = cs * (x2 - x1) * (y1 - y2) * rden * 0.5f;
    float t3 = 0.5f * __logf(denom * __fdividef(1.f, 4.f * sqrtf(det1 * det2) + eps) + eps);
    float bd = fminf(fmaxf(t1 + t2 + t3, eps), 100.f);
    return sqrtf(1.f - __expf(-bd) + 1e-7f);
}

__device__ __forceinline__ float warpSum(float v) {
    #pragma unroll
    for (int o = 16; o; o >>= 1) v += __shfl_xor_sync(FULLM, v, o);
    return v;
}

__device__ __forceinline__ float focal_bg(float x) {
    float e = __expf(-fabsf(x));
    float den = 1.f + e;
    float rden = __fdividef(1.f, den);
    float p = (x >= 0.f) ? rden : e * rden;
    float bce = fmaxf(x, 0.f) + __logf(den);
    return bce * 0.75f * p * p;
}

// ------------------------------------------------------------------ kernels
// Per-gt precompute + maxAI reset (claim array reset incrementally by the
// previous replay's k_loss_final; zero-state is valid).
__global__ void __launch_bounds__(256) k_init(const float* __restrict__ gbox,
                                              const int*   __restrict__ glab,
                                              const float* __restrict__ vmask) {
    int i = blockIdx.x * 256 + threadIdx.x;
    if (i < Bb * Mm) {
        float gx = gbox[i * 5 + 0], gy = gbox[i * 5 + 1];
        float gw = gbox[i * 5 + 2], gh = gbox[i * 5 + 3], ga = gbox[i * 5 + 4];
        float ca, sa; __sincosf(ga, &sa, &ca);
        float A = gw * gw * (1.f/12.f), B = gh * gh * (1.f/12.f);
        float va = A * ca * ca + B * sa * sa;
        float vb = A * sa * sa + B * ca * ca;
        float vc = (A - B) * ca * sa;
        float det = fmaxf(va * vb - vc * vc, 0.f);
        float r = 0.5f * sqrtf(gw * gw + gh * gh);
        float t = fminf(fmaxf(ga / ANGLE_SCALE_F, 0.f), 89.99f);
        int li = (int)t;
        int ri = min(li + 1, 90);
        float lw = (float)ri - t;
        d_gprep[i * 4 + 0] = make_float4(gx, gy, va, vb);
        d_gprep[i * 4 + 1] = make_float4(vc, det, r, lw);
        d_gprep[i * 4 + 2] = make_float4(ca, sa, gw * 0.5f, gh * 0.5f);
        d_gprep[i * 4 + 3] = make_float4(__int_as_float(li), __int_as_float(glab[i]),
                                         vmask[i], 0.f);
        d_maxAI[i] = make_uint2(0u, 0u);
    }
}

// Warp per 4 anchors, 8 lanes per anchor. Pure decode now (BCE moved to topk).
__global__ void __launch_bounds__(256) k_decode(const float* __restrict__ reg,
                                                const float* __restrict__ ang) {
    int tid = threadIdx.x;
    int wid = tid >> 5, lane = tid & 31;
    int abase = blockIdx.x * 32 + wid * 4;
    int j = lane >> 3;          // anchor within group
    int s = lane & 7;           // sub-lane within anchor
    int ga = abase + j;
    const float* row = ang + (size_t)ga * Aa;

    float ssum = 0.f, wsum = 0.f;
    float fi = (float)s;
    #pragma unroll
    for (int k = 0; k < 11; k++) {
        float p = __expf(row[s + 8 * k]);
        ssum += p;
        wsum = fmaf(fi, p, wsum);
        fi += 8.f;
    }
    if (s < 3) {
        float p = __expf(row[s + 88]);
        ssum += p;
        wsum = fmaf((float)(s + 88), p, wsum);
    }
    #pragma unroll
    for (int o = 4; o; o >>= 1) {
        ssum += __shfl_xor_sync(FULLM, ssum, o);
        wsum += __shfl_xor_sync(FULLM, wsum, o);
    }

    if (s == 0) {
        float angle = ANGLE_SCALE_F * __fdividef(wsum, ssum);
        float Z = __logf(ssum);
        const float4 rd = ((const float4*)reg)[ga];   // lt=(x,y) rb=(z,w)
        float offx = (rd.z - rd.x) * 0.5f, offy = (rd.w - rd.y) * 0.5f;
        float c, sn; __sincosf(angle, &sn, &c);
        float ox = offx * c - offy * sn;
        float oy = offx * sn + offy * c;
        int n = ga % Nn;
        float ax, ay, st;
        if (n < 16384)      { ax = ((n & 127) + 0.5f) * 8.f;  ay = ((n >> 7) + 0.5f) * 8.f;  st = 8.f;  }
        else if (n < 20480) { int k = n - 16384; ax = ((k & 63) + 0.5f) * 16.f; ay = ((k >> 6) + 0.5f) * 16.f; st = 16.f; }
        else                { int k = n - 20480; ax = ((k & 31) + 0.5f) * 32.f; ay = ((k >> 5) + 0.5f) * 32.f; st = 32.f; }
        float X = ox * st + ax, Y = oy * st + ay;
        float W = (rd.x + rd.z) * st, H = (rd.y + rd.w) * st;
        float A = W * W * (1.f/12.f), B = H * H * (1.f/12.f);
        float va = A * c * c + B * sn * sn;
        float vb = A * sn * sn + B * c * c;
        float vc = (A - B) * c * sn;
        float det = fmaxf(va * vb - vc * vc, 0.f);
        float4* pp = (float4*)(d_pred + (size_t)ga * 8);
        pp[0] = make_float4(X, Y, va, vb);
        pp[1] = make_float4(vc, det, Z, 0.f);
    }
}

// Profiling spacer so the ncu capture slot (launch idx 3) lands on k_topk.
__global__ void k_noop() {}

// One block (128 thr) per (b,m): grid-stride background focal-BCE (fills the
// latency-bound kernel's idle issue slots), then candidate collection,
// per-warp exact top-13, warp-0 merge. 2 block barriers total.
__global__ void __launch_bounds__(128) k_topk(const float* __restrict__ cls,
                                              const float4* __restrict__ cls4) {
    __shared__ unsigned long long sKey[NC];
    __shared__ unsigned long long sW[52];     // 4 warps x 13 winners
    __shared__ int sCnt;

    int tid = threadIdx.x;
    int wid = tid >> 5, lane = tid & 31;

    // ---- background focal-BCE share (all blocks, incl. pad-gt ones) ----
    {
        float acc = 0.f;
        for (int i = blockIdx.x * 128 + tid; i < NF4; i += Bb * Mm * 128) {
            float4 v = cls4[i];
            acc += focal_bg(v.x) + focal_bg(v.y) + focal_bg(v.z) + focal_bg(v.w);
        }
        acc = warpSum(acc);
        if (lane == 0) atomicAdd(&d_acc[0], acc);
    }

    int bm = blockIdx.x;
    int b = bm >> 6, m = bm & 63;
    const float4 q0 = d_gprep[bm * 4 + 0];
    const float4 q1 = d_gprep[bm * 4 + 1];
    const float4 q2 = d_gprep[bm * 4 + 2];
    const float4 q3 = d_gprep[bm * 4 + 3];
    if (q3.z == 0.f) return;      // pad gt

    const float gx = q0.x, gy = q0.y, gva = q0.z, gvb = q0.w;
    const float gvc = q1.x, gdet = q1.y, r = q1.z;
    const float ca = q2.x, sa = q2.y, hw = q2.z, hh = q2.w;
    const int lbl = __float_as_int(q3.y);

    if (tid == 0) sCnt = 0;
    if (tid < 52) sW[tid] = 0ull;
    __syncthreads();

    const int   baseL[3] = {0, 16384, 20480};
    const int   ngL[3]   = {128, 64, 32};
    const float sL[3]    = {8.f, 16.f, 32.f};
    #pragma unroll
    for (int L = 0; L < 3; L++) {
        float s = sL[L]; int ng = ngL[L];
        float inv = 1.f / s;
        int ix0 = max(0,      (int)floorf((gx - r) * inv - 0.5f));
        int ix1 = min(ng - 1, (int)ceilf ((gx + r) * inv - 0.5f));
        int iy0 = max(0,      (int)floorf((gy - r) * inv - 0.5f));
        int iy1 = min(ng - 1, (int)ceilf ((gy + r) * inv - 0.5f));
        if (ix1 < ix0 || iy1 < iy0) continue;
        int W = ix1 - ix0 + 1;
        int tot = W * (iy1 - iy0 + 1);
        for (int t0 = 0; t0 < tot; t0 += 128) {
            int t = t0 + tid;
            bool act = false;
            unsigned long long key = 0ull;
            if (t < tot) {
                int q = t / W;
                int ix = ix0 + (t - q * W);
                int iy = iy0 + q;
                float ax = (ix + 0.5f) * s, ay = (iy + 0.5f) * s;
                float dx = ax - gx, dy = ay - gy;
                float xr = dx * ca + dy * sa;
                float yr = -dx * sa + dy * ca;
                if (fabsf(xr) < hw && fabsf(yr) < hh) {
                    int n = baseL[L] + iy * ng + ix;
                    int gi = b * Nn + n;
                    const float4* pp = (const float4*)(d_pred + (size_t)gi * 8);
                    float4 p0 = pp[0], p1 = pp[1];
                    float hd = probiou_pre(gx, gy, gva, gvb, gvc, gdet,
                                           p0.x, p0.y, p0.z, p0.w, p1.x, p1.y);
                    float iou = fmaxf(1.f - hd, 0.f);
                    float x = cls[(size_t)gi * Cc + lbl];
                    float sg = __fdividef(1.f, 1.f + __expf(-x));
                    float i2 = iou * iou;
                    float al = sg * i2 * i2 * i2;
                    if (al > 1e-9f) {
                        act = true;
                        key = ((unsigned long long)__float_as_uint(al) << 32)
                            | (unsigned)(0x7fffffff - n);
                    }
                }
            }
            unsigned mask = __ballot_sync(FULLM, act);
            if (mask) {
                int base = 0;
                if (lane == 0) base = atomicAdd(&sCnt, __popc(mask));
                base = __shfl_sync(FULLM, base, 0);
                if (act) {
                    int off = base + __popc(mask & ((1u << lane) - 1u));
                    if (off < NC) sKey[off] = key;
                }
            }
        }
    }
    __syncthreads();
    int cnt = min(sCnt, NC);

    // per-warp exact top-13 over its strided quarter (sync-free)
    #pragma unroll 1
    for (int k = 0; k < KTOP; k++) {
        unsigned long long best = 0ull; int bs = -1;
        for (int s = wid * 32 + lane; s < cnt; s += 128) {
            unsigned long long v = sKey[s];
            if (v > best) { best = v; bs = s; }
        }
        #pragma unroll
        for (int o = 16; o; o >>= 1) {
            unsigned long long ov = __shfl_xor_sync(FULLM, best, o);
            int os = __shfl_xor_sync(FULLM, bs, o);
            if (ov > best) { best = ov; bs = os; }
        }
        if (best == 0ull) break;
        if (lane == 0) { sW[wid * KTOP + k] = best; sKey[bs] = 0ull; }
    }
    __syncthreads();

    // warp 0 merges the 52 warp-winners; round-k winner in lane k's register
    if (wid == 0) {
        unsigned long long v0 = (lane < 52) ? sW[lane] : 0ull;
        unsigned long long v1 = (lane + 32 < 52) ? sW[lane + 32] : 0ull;
        unsigned long long mykey = 0ull;
        int nfin = 0;
        #pragma unroll 1
        for (int k = 0; k < KTOP; k++) {
            unsigned long long best = (v0 > v1) ? v0 : v1;
            #pragma unroll
            for (int o = 16; o; o >>= 1) {
                unsigned long long ov = __shfl_xor_sync(FULLM, best, o);
                if (ov > best) best = ov;
            }
            if (best == 0ull) break;
            if (v0 == best) v0 = 0ull;
            if (v1 == best) v1 = 0ull;
            if (lane == k) mykey = best;
            nfin++;
        }
        if (nfin) {
            int base = 0;
            if (lane == 0) base = atomicAdd(&d_listcnt, nfin);
            base = __shfl_sync(FULLM, base, 0);
            if (lane < nfin) {
                int n = 0x7fffffff - (int)(mykey & 0xffffffffu);
                float al = __uint_as_float((unsigned)(mykey >> 32));
                int gi = b * Nn + n;
                atomicAdd(&d_claim[gi].x, 1);
                atomicMax(&d_claim[gi].y, 0x7fffffff - m);
                const float4* pp = (const float4*)(d_pred + (size_t)gi * 8);
                float4 p0 = pp[0], p1 = pp[1];
                float hd = probiou_pre(gx, gy, gva, gvb, gvc, gdet,
                                       p0.x, p0.y, p0.z, p0.w, p1.x, p1.y);
                d_rec[base + lane] = make_float4(__int_as_float(gi), __int_as_float(m),
                                                 al, hd);
            }
        }
    }
}

// ONE WARP PER RECORD (8 records/block, grid = NREC/8): election,
// lane-parallel 64-gt argmax for multi-claimed anchors, angle-CE + npos,
// maxAI atomics, flagged write to d_e[record].
__global__ void __launch_bounds__(256) k_resolve(const float* __restrict__ cls,
                                                 const float* __restrict__ ang) {
    __shared__ float sc3, sc4;
    int tid = threadIdx.x;
    int wid = tid >> 5, lane = tid & 31;
    if (tid == 0) { sc3 = 0.f; sc4 = 0.f; }
    __syncthreads();

    int wrec = blockIdx.x * 8 + wid;
    int lc = d_listcnt;
    if (wrec < lc) {
        float4 rec = d_rec[wrec];                    // uniform across warp
        int gi = __float_as_int(rec.x);
        int m  = __float_as_int(rec.y);
        float align = rec.z, hd = rec.w;
        int2 cl = d_claim[gi];                       // uniform
        bool elected = (cl.y == 0x7fffffff - m);
        int b = gi / Nn;
        int tgt = m;
        if (elected) {
            if (cl.x > 1) {
                // lane-parallel argmax over all 64 gts (2 per lane)
                const float4* pp = (const float4*)(d_pred + (size_t)gi * 8);
                float4 p0 = pp[0], p1 = pp[1];
                float bi = -1.f, bh = 0.f; int bmm = 0;
                #pragma unroll
                for (int j = 0; j < 2; j++) {
                    int mm = lane + j * 32;
                    float4 g0 = d_gprep[(b * Mm + mm) * 4 + 0];
                    float4 g1 = d_gprep[(b * Mm + mm) * 4 + 1];
                    float h = probiou_pre(g0.x, g0.y, g0.z, g0.w, g1.x, g1.y,
                                          p0.x, p0.y, p0.z, p0.w, p1.x, p1.y);
                    float io = fmaxf(1.f - h, 0.f);
                    if (io > bi) { bi = io; bh = h; bmm = mm; }
                }
                #pragma unroll
                for (int o = 16; o; o >>= 1) {
                    float ov = __shfl_xor_sync(FULLM, bi, o);
                    float oh = __shfl_xor_sync(FULLM, bh, o);
                    int   om = __shfl_xor_sync(FULLM, bmm, o);
                    if (ov > bi || (ov == bi && om < bmm)) { bi = ov; bh = oh; bmm = om; }
                }
                tgt = bmm; hd = bh;
                int lbl = __float_as_int(d_gprep[(b * Mm + tgt) * 4 + 3].y);
                float x = cls[(size_t)gi * Cc + lbl];    // same addr all lanes
                float sg = __fdividef(1.f, 1.f + __expf(-x));
                float i2 = bi * bi;
                align = sg * i2 * i2 * i2;
            }
            if (lane == 0) {
                int ebm = b * Mm + tgt;
                atomicMax(&d_maxAI[ebm].x, __float_as_uint(align));
                atomicMax(&d_maxAI[ebm].y, __float_as_uint(fmaxf(1.f - hd, 0.f)));
                float4 g1 = d_gprep[ebm * 4 + 1];
                float4 g3 = d_gprep[ebm * 4 + 3];
                float lw = g1.w;
                int li = __float_as_int(g3.x);
                int ri = min(li + 1, 90);
                float Z = d_pred[(size_t)gi * 8 + 6];
                const float* xr = ang + (size_t)gi * Aa;
                float c3 = (Z - __ldg(xr + li)) * lw + (Z - __ldg(xr + ri)) * (1.f - lw);
                atomicAdd(&sc3, c3);
                atomicAdd(&sc4, 1.f);
                d_e[wrec] = make_float4(__int_as_float(gi), __int_as_float(ebm),
                                        align, hd);
            }
        } else if (lane == 0) {
            d_e[wrec] = make_float4(0.f, __int_as_float(-1), 0.f, 0.f);
        }
    }
    __syncthreads();
    if (tid == 0 && (sc3 != 0.f || sc4 != 0.f)) {
        atomicAdd(&d_acc[3], sc3);
        atomicAdd(&d_acc[4], sc4);
    }
}

// One thread per record slot: flagged loss terms + claim reset; last block
// finalizes output and resets scalars.
__global__ void __launch_bounds__(128) k_loss_final(const float* __restrict__ cls,
                                                    float* __restrict__ out, int osz) {
    __shared__ bool isLast;
    int tid = threadIdx.x;
    int idx = blockIdx.x * 128 + tid;
    int lane = tid & 31;
    int lc = d_listcnt;

    float c0 = 0.f, c1 = 0.f, c2 = 0.f;
    if (idx < lc) {
        float4 en = d_e[idx];
        int bm2 = __float_as_int(en.y);
        if (bm2 >= 0) {
            int egi = __float_as_int(en.x);
            float al = en.z, h = en.w;
            uint2 mx = d_maxAI[bm2];
            float na = al * __uint_as_float(mx.y) *
                       __fdividef(1.f, __uint_as_float(mx.x) + 1e-9f);
            int lbl = __float_as_int(d_gprep[bm2 * 4 + 3].y);
            float x = cls[(size_t)egi * Cc + lbl];
            float ex = __expf(-fabsf(x));
            float den = 1.f + ex;
            float rden = __fdividef(1.f, den);
            float p = (x >= 0.f) ? rden : ex * rden;
            float bce0 = fmaxf(x, 0.f) + __logf(den);
            c0 = (bce0 - x * na) * na - bce0 * 0.75f * p * p;
            c1 = na;
            c2 = h * na;
        }
        // distributed claim reset for next replay (duplicates idempotent)
        int rgi = __float_as_int(d_rec[idx].x);
        d_claim[rgi] = make_int2(0, 0);
    }

    c0 = warpSum(c0); c1 = warpSum(c1); c2 = warpSum(c2);
    if (lane == 0) {
        atomicAdd(&d_acc[0], c0); atomicAdd(&d_acc[1], c1); atomicAdd(&d_acc[2], c2);
    }

    __syncthreads();
    if (tid == 0) {
        __threadfence();
        unsigned prev = atomicAdd(&d_done, 1u);
        isLast = (prev == gridDim.x - 1);
    }
    __syncthreads();
    if (!isLast) return;
    if (tid == 0) {
        __threadfence();
        float clsn = d_acc[0];
        float ss   = fmaxf(d_acc[1], 1.f);
        float boxn = d_acc[2];
        float angn = d_acc[3];
        float npos = fmaxf(d_acc[4], 1.f);
        float lcv = clsn / ss;
        float lbv = boxn / ss;
        float lav = angn / npos;
        float tot = lcv + 2.5f * lbv + 0.05f * lav;
        if (osz >= 4) { out[0] = tot; out[1] = lcv; out[2] = lbv; out[3] = lav; }
        else if (osz >= 1) out[0] = tot;
        // reset scalars for next replay
        #pragma unroll
        for (int i2 = 0; i2 < 8; i2++) d_acc[i2] = 0.f;
        d_listcnt = 0;
        __threadfence();
        d_done = 0u;
    }
}

// ------------------------------------------------------------------ launch
extern "C" void kernel_launch(void* const* d_in, const int* in_sizes, int n_in,
                              void* d_out, int out_size) {
    const float* cls   = (const float*)d_in[0];   // (B,N,C)
    const float* reg   = (const float*)d_in[1];   // (B,N,4)
    const float* ang   = (const float*)d_in[2];   // (B,N,91)
    const int*   glab  = (const int*)  d_in[3];   // (B,M,1)
    const float* gbox  = (const float*)d_in[4];   // (B,M,5)
    const float* vmask = (const float*)d_in[5];   // (B,M,1)
    float* out = (float*)d_out;

    k_init      <<<4, 256>>>(gbox, glab, vmask);                        // idx 0
    k_decode    <<<NTOT / 32, 256>>>(reg, ang);                         // idx 1
    k_noop      <<<1, 32>>>();                                          // idx 2 (spacer)
    k_topk      <<<Bb * Mm, 128>>>(cls, (const float4*)cls);            // idx 3 (ncu capture)
    k_resolve   <<<NREC / 8, 256>>>(cls, ang);                          // idx 4
    k_loss_final<<<NREC / 128, 128>>>(cls, out, out_size);              // idx 5
}